// round 14
// baseline (speedup 1.0000x reference)
#include <cuda_runtime.h>
#include <cuda_fp16.h>
#include <math.h>
#include <stdint.h>

// CharsLstm B=64 T=512 E=256 H=1024 V=256 — one-term fp16, warp-autonomous.
//
// gates[4096,64] = f16(W) @ f16(h).  W resident in SMEM; h exchanged through
// global with PER-BLOCK release flags (st.release / parallel lane polling,
// no atomics). Each warp-PAIR (warpN,warpK) owns a disjoint B slice
// (16 batches x 512 k) in dedicated smem, fetches it autonomously with
// cp.async (2 chunk groups, fetch/compute overlapped), and syncs only with
// its partner via a named barrier. Block-wide syncs: 3/step (reduce x2,
// pre-release). 128 persistent blocks (1/SM) x 512 threads; c in registers;
// HW activations.
//
// WAR safety on g_h: block P writes buffer g_h[t&1] at step t+2 only after
// ALL its pairs' polls passed (flags >= t+2 for all 128 producers, since the
// pairs collectively cover all 4 chunks), i.e. after every consumer block
// finished step t+1 — which is when the step-t data in that buffer was last
// read. Release (flag=t+1) happens after the pre-release syncthreads, i.e.
// after all reads and writes of step t in that block.

#define BB   64
#define TT   512
#define HH   1024
#define GG   4096
#define NBLK 128
#define NTHR 512

#define WP_B   2064                   // W smem row pitch bytes (1032 halfs)
#define BP_B   1040                   // B slice row pitch bytes (520 halfs)
#define PAIR_SZ (16 * BP_B)           // 16 rows x 512 k (+pad) = 16640 B
#define OFF_GS  256
#define OFF_W   8704                  // 256 + 32*66*4
#define OFF_B   (OFF_W + 32 * WP_B)   // 74752
#define SMEM_BYTES (OFF_B + 8 * PAIR_SZ)      // 207872

__device__ __half   g_W[GG * HH];             // 8 MB (fp16 W)
__device__ __half   g_h[2][BB * HH];          // ping-pong hidden (f16)
__device__ float    g_table[256 * GG];        // 4 MB
__device__ unsigned g_flag[NBLK];             // per-block completed-step count

// ---------------------------------------------------------------- helpers
__device__ __forceinline__ uint32_t smem_u32(const void* p) {
    uint32_t a;
    asm("{ .reg .u64 t; cvta.to.shared.u64 t, %1; cvt.u32.u64 %0, t; }"
        : "=r"(a) : "l"(p));
    return a;
}
__device__ __forceinline__ unsigned ld_acq(const unsigned* p) {
    unsigned v;
    asm volatile("ld.acquire.gpu.global.u32 %0, [%1];" : "=r"(v) : "l"(p));
    return v;
}
__device__ __forceinline__ void st_release(unsigned* p, unsigned v) {
    asm volatile("st.release.gpu.global.u32 [%0], %1;"
                 :: "l"(p), "r"(v) : "memory");
}
__device__ __forceinline__ float fast_sigmoid(float v) {
    float e, r;
    asm("ex2.approx.f32 %0, %1;" : "=f"(e) : "f"(v * -1.4426950408889634f));
    asm("rcp.approx.f32 %0, %1;" : "=f"(r) : "f"(1.f + e));
    return r;
}
__device__ __forceinline__ float fast_tanh(float v) {
    float r;
    asm("tanh.approx.f32 %0, %1;" : "=f"(r) : "f"(v));
    return r;
}
// all 32 lanes poll the 32 producer flags of one chunk in parallel
__device__ __forceinline__ void poll_chunk(int chunk, unsigned need, int lane) {
    const unsigned* p = &g_flag[chunk * 32 + lane];
    unsigned f = ld_acq(p);
    while (__any_sync(0xffffffffu, f < need)) { f = ld_acq(p); }
}
#define PAIR_BAR(id)                                                        \
    asm volatile("bar.sync %0, 64;" :: "r"(id) : "memory")
#define LDSM4(r0, r1, r2, r3, a)                                            \
    asm volatile("ldmatrix.sync.aligned.m8n8.x4.shared.b16 {%0,%1,%2,%3}, [%4];" \
        : "=r"(r0), "=r"(r1), "=r"(r2), "=r"(r3) : "r"(a))
#define MMA16816(d0, d1, d2, d3, a0, a1, a2, a3, b0, b1)                    \
    asm volatile("mma.sync.aligned.m16n8k16.row.col.f32.f16.f16.f32 "       \
        "{%0,%1,%2,%3}, {%4,%5,%6,%7}, {%8,%9}, {%0,%1,%2,%3};"             \
        : "+f"(d0), "+f"(d1), "+f"(d2), "+f"(d3)                            \
        : "r"(a0), "r"(a1), "r"(a2), "r"(a3), "r"(b0), "r"(b1))
#define CP_ASYNC16(dst, src)                                                \
    asm volatile("cp.async.cg.shared.global [%0], [%1], 16;"                \
        :: "r"(dst), "l"(src) : "memory")
#define CP_COMMIT()  asm volatile("cp.async.commit_group;" ::: "memory")
#define CP_WAIT(n)   asm volatile("cp.async.wait_group %0;" :: "n"(n) : "memory")

// ---------------------------------------------------------------- setup
__global__ void table_kernel(const float* __restrict__ emb,
                             const float* __restrict__ W_ih,
                             const float* __restrict__ b_ih,
                             const float* __restrict__ b_hh) {
    __shared__ float embs[32 * 65];
    __shared__ float wch[64 * 129];
    const int g  = threadIdx.x;
    const int gt = blockIdx.x, vt = blockIdx.y;
    float acc[32];
#pragma unroll
    for (int v = 0; v < 32; v++) acc[v] = 0.f;

    for (int ch = 0; ch < 4; ch++) {
        __syncthreads();
        for (int i = g; i < 2048; i += 128) {
            int v = i >> 6, e = i & 63;
            embs[v * 65 + e] = emb[(vt * 32 + v) * 256 + ch * 64 + e];
        }
        {
            const float4* src = (const float4*)(W_ih + (size_t)(gt * 128 + g) * 256 + ch * 64);
#pragma unroll
            for (int q = 0; q < 16; q++) {
                float4 w = src[q];
                wch[(q * 4 + 0) * 129 + g] = w.x;
                wch[(q * 4 + 1) * 129 + g] = w.y;
                wch[(q * 4 + 2) * 129 + g] = w.z;
                wch[(q * 4 + 3) * 129 + g] = w.w;
            }
        }
        __syncthreads();
#pragma unroll 4
        for (int e = 0; e < 64; e++) {
            float w = wch[e * 129 + g];
#pragma unroll
            for (int v = 0; v < 32; v++) acc[v] += w * embs[v * 65 + e];
        }
    }
    int col = gt * 128 + g;
    float bias = b_ih[col] + b_hh[col];
#pragma unroll
    for (int v = 0; v < 32; v++) {
        int tok = vt * 32 + v;
        g_table[(size_t)tok * GG + col] = (tok == 0 ? 0.f : acc[v]) + bias;
    }
}

__global__ void pack_w_kernel(const float* __restrict__ Whh) {
    int idx = blockIdx.x * 256 + threadIdx.x;
    g_W[idx] = __float2half(Whh[idx]);
}

__global__ void init_kernel(const float* __restrict__ h0) {
    int i = blockIdx.x * 256 + threadIdx.x;
    g_h[1][i] = __float2half(h0[i]);          // t=0 reads buffer (0+1)&1 = 1
    if (i < NBLK) g_flag[i] = 0;
}

// ---------------------------------------------------------------- main
__global__ void __launch_bounds__(NTHR, 1)
step_all(const int* __restrict__ x,
         const float* __restrict__ c0,
         float* __restrict__ out) {
    extern __shared__ __align__(16) unsigned char sm[];
    const uint32_t smb = smem_u32(sm);
    float* gs = (float*)(sm + OFF_GS);        // [32 rows][pitch 66]

    const int tid   = threadIdx.x;
    const int bid   = blockIdx.x;
    const int lane  = tid & 31;
    const int warp  = tid >> 5;
    const int warpM = warp & 1;               // 2 x m16
    const int warpN = (warp >> 1) & 3;        // 4 x n16 (batch groups)
    const int warpK = warp >> 3;              // 2-way k-halves (512 each)
    const int pairId = warp >> 1;             // 0..7 (warpN,warpK)
    const uint32_t pairBase = smb + OFF_B + (uint32_t)pairId * PAIR_SZ;

    // ---- stage W slice once (block rows: gate*8 + jj) ----
#pragma unroll
    for (int j = 0; j < 8; j++) {
        int i = j * NTHR + tid;               // 4096 float4
        int row = i >> 7, q = i & 127;
        int grow = (row >> 3) * HH + bid * 8 + (row & 7);
        *(float4*)(sm + OFF_W + row * WP_B + q * 16) =
            __ldcg((const float4*)(g_W + (size_t)grow * HH) + q);
    }

    // ---- ldmatrix bases ----
    const int rowA  = warpM * 16 + (lane & 15);
    const int kOffA = (lane >> 4) * 8;
    const uint32_t aBase = smb + OFF_W + rowA * WP_B + kOffA * 2
                         + (uint32_t)warpK * 1024;     // k-half (512 halfs)
    const int nLoc  = ((lane >> 4) & 1) * 8 + (lane & 7);   // row in pair slice
    const int kOffB = ((lane >> 3) & 1) * 8;
    const uint32_t bBase = pairBase + nLoc * BP_B + kOffB * 2;

    // fetch indexing: this warp covers local rows warpM*8..+8 of the pair
    const int fRowBase = warpN * 16 + warpM * 8;             // global batch
    const uint32_t fDstBase = pairBase + (uint32_t)(warpM * 8) * BP_B;

    // cell state: 1 cell per thread (unit jj, batch bb)
    const int jj = tid & 7, bb = tid >> 3;
    float creg = c0[bb * HH + bid * 8 + jj];
    const int J = bid * 8 + jj;

    __syncthreads();

#pragma unroll 1
    for (int t = 0; t < TT; t++) {
        const __half* __restrict__ hh = g_h[(t + 1) & 1];

        // early per-thread prefetch: token + the 4 table entries for the cell
        const int tok = __ldg(&x[bb * TT + t]);
        const float* trow = g_table + (size_t)tok * GG + J;
        float tb0 = __ldg(trow);
        float tb1 = __ldg(trow + HH);
        float tb2 = __ldg(trow + 2 * HH);
        float tb3 = __ldg(trow + 3 * HH);

        const unsigned need = (unsigned)t;

        // ---- pair-autonomous poll + fetch of its two 256-k chunks ----
#pragma unroll
        for (int cL = 0; cL < 2; cL++) {
            const int chunk = 2 * warpK + cL;
            if (t > 0) poll_chunk(chunk, need, lane);
            const __half* src = hh + (size_t)fRowBase * HH
                              + warpK * 512 + cL * 256;
            const uint32_t dst = fDstBase + (uint32_t)cL * 512;
#pragma unroll
            for (int q8 = 0; q8 < 8; q8++) {
                int q  = q8 * 32 + lane;      // 0..255
                int r  = q >> 5;              // 0..7
                int kq = q & 31;              // 16B units
                CP_ASYNC16(dst + r * BP_B + kq * 16, src + r * HH + kq * 8);
            }
            CP_COMMIT();
        }

        // ---- GEMM: chunk A while chunk B lands ----
        float d00=0,d01=0,d02=0,d03=0, d10=0,d11=0,d12=0,d13=0;
        CP_WAIT(1);
        PAIR_BAR(1 + pairId);
#pragma unroll
        for (int kk = 0; kk < 16; kk++) {
            uint32_t a0,a1,a2,a3, b0,b1,b2,b3;
            LDSM4(a0,a1,a2,a3, aBase + kk * 32);
            LDSM4(b0,b1,b2,b3, bBase + kk * 32);
            MMA16816(d00,d01,d02,d03, a0,a1,a2,a3, b0,b1);
            MMA16816(d10,d11,d12,d13, a0,a1,a2,a3, b2,b3);
        }
        CP_WAIT(0);
        PAIR_BAR(1 + pairId);
#pragma unroll
        for (int kk = 16; kk < 32; kk++) {
            uint32_t a0,a1,a2,a3, b0,b1,b2,b3;
            LDSM4(a0,a1,a2,a3, aBase + kk * 32);
            LDSM4(b0,b1,b2,b3, bBase + kk * 32);
            MMA16816(d00,d01,d02,d03, a0,a1,a2,a3, b0,b1);
            MMA16816(d10,d11,d12,d13, a0,a1,a2,a3, b2,b3);
        }

        // ---- split-K reduce into gs[row][b] ----
        const int r0  = warpM * 16 + (lane >> 2);
        const int c0i = warpN * 16 + (lane & 3) * 2;
        if (warpK == 1) {
            *(float2*)(gs + (r0    ) * 66 + c0i    ) = make_float2(d00, d01);
            *(float2*)(gs + (r0 + 8) * 66 + c0i    ) = make_float2(d02, d03);
            *(float2*)(gs + (r0    ) * 66 + c0i + 8) = make_float2(d10, d11);
            *(float2*)(gs + (r0 + 8) * 66 + c0i + 8) = make_float2(d12, d13);
        }
        __syncthreads();                       // sync #1
        if (warpK == 0) {
            float2* p;
            p = (float2*)(gs + (r0    ) * 66 + c0i    ); p->x += d00; p->y += d01;
            p = (float2*)(gs + (r0 + 8) * 66 + c0i    ); p->x += d02; p->y += d03;
            p = (float2*)(gs + (r0    ) * 66 + c0i + 8); p->x += d10; p->y += d11;
            p = (float2*)(gs + (r0 + 8) * 66 + c0i + 8); p->x += d12; p->y += d13;
        }
        __syncthreads();                       // sync #2

        // ---- fused LSTM cell: 1 cell per thread (HW activations) ----
        __half* __restrict__ nh = g_h[t & 1];
        {
            float ipre = gs[(0 * 8 + jj) * 66 + bb] + tb0;
            float fpre = gs[(1 * 8 + jj) * 66 + bb] + tb1;
            float gpre = gs[(2 * 8 + jj) * 66 + bb] + tb2;
            float opre = gs[(3 * 8 + jj) * 66 + bb] + tb3;
            float isg = fast_sigmoid(ipre);
            float fsg = fast_sigmoid(fpre);
            float gth = fast_tanh(gpre);
            float osg = fast_sigmoid(opre);
            float cv = fsg * creg + isg * gth;
            creg = cv;
            float hv = osg * fast_tanh(cv);
            nh[bb * HH + J] = __float2half(hv);
            if (t == TT - 1) out[bb * HH + J] = hv;
        }

        // ---- release: this block completed step t ----
        __syncthreads();                       // sync #3
        if (t < TT - 1 && tid == 0) {
            st_release(&g_flag[bid], (unsigned)(t + 1));
        }
    }
}

// ---------------------------------------------------------------------------
extern "C" void kernel_launch(void* const* d_in, const int* in_sizes, int n_in,
                              void* d_out, int out_size) {
    const int*   x   = (const int*)  d_in[0];
    const float* emb = (const float*)d_in[1];
    const float* Wih = (const float*)d_in[2];
    const float* Whh = (const float*)d_in[3];
    const float* bih = (const float*)d_in[4];
    const float* bhh = (const float*)d_in[5];
    const float* h0  = (const float*)d_in[6];
    const float* c0  = (const float*)d_in[7];
    float*       out = (float*)d_out;

    static int attr_set = 0;
    if (!attr_set) {
        cudaFuncSetAttribute(step_all,
                             cudaFuncAttributeMaxDynamicSharedMemorySize,
                             SMEM_BYTES);
        attr_set = 1;
    }

    table_kernel<<<dim3(32, 8), 128>>>(emb, Wih, bih, bhh);
    pack_w_kernel<<<(GG * HH) / 256, 256>>>(Whh);
    init_kernel<<<(BB * HH) / 256, 256>>>(h0);
    step_all<<<NBLK, NTHR, SMEM_BYTES>>>(x, c0, out);
}

// round 15
// speedup vs baseline: 1.3359x; 1.3359x over previous
#include <cuda_runtime.h>
#include <cuda_fp16.h>
#include <math.h>
#include <stdint.h>

// CharsLstm B=64 T=512 E=256 H=1024 V=256 — one-term fp16 on R11 structure.
//
// gates[4096,64] = f16(W) @ f16(h)   (rel_err ~1.5e-4, confirmed R13/R14).
// R15 = R11 verbatim minus the Wlo plane (single MMA term). 128 persistent
// blocks (1/SM) x 512 threads; W slice (66KB) resident in SMEM; h ping-pong
// f16 in global, cp.async double-buffered 32KB chunks with rotated per-block
// schedule; per-chunk step counters (no grid barrier); c in registers;
// HW activations (ex2/rcp/tanh.approx).

#define BB   64
#define TT   512
#define HH   1024
#define GG   4096
#define NBLK 128
#define NTHR 512

#define WP_B   2064                   // W smem row pitch bytes (1032 halfs)
#define HP_B   528                    // h chunk row pitch bytes (264 halfs)
#define OFF_GS  256
#define OFF_W   8704                  // 256 + 32*66*4
#define OFF_HS0 (OFF_W + 32 * WP_B)   // 74752
#define OFF_HS1 (OFF_HS0 + 64 * HP_B) // +33792
#define SMEM_BYTES (OFF_HS1 + 64 * HP_B)      // 142336

__device__ __half   g_W[GG * HH];             // 8 MB (fp16 W)
__device__ __half   g_h[2][BB * HH];          // ping-pong hidden (f16)
__device__ float    g_table[256 * GG];        // 4 MB
__device__ unsigned g_cnt[4];                 // per-256k-chunk step counters

// ---------------------------------------------------------------- helpers
__device__ __forceinline__ uint32_t smem_u32(const void* p) {
    uint32_t a;
    asm("{ .reg .u64 t; cvta.to.shared.u64 t, %1; cvt.u32.u64 %0, t; }"
        : "=r"(a) : "l"(p));
    return a;
}
__device__ __forceinline__ unsigned ld_acq(const unsigned* p) {
    unsigned v;
    asm volatile("ld.acquire.gpu.global.u32 %0, [%1];" : "=r"(v) : "l"(p));
    return v;
}
__device__ __forceinline__ void red_release(unsigned* p, unsigned v) {
    asm volatile("red.release.gpu.global.add.u32 [%0], %1;"
                 :: "l"(p), "r"(v) : "memory");
}
__device__ __forceinline__ float fast_sigmoid(float v) {
    float e, r;
    asm("ex2.approx.f32 %0, %1;" : "=f"(e) : "f"(v * -1.4426950408889634f));
    asm("rcp.approx.f32 %0, %1;" : "=f"(r) : "f"(1.f + e));
    return r;
}
__device__ __forceinline__ float fast_tanh(float v) {
    float r;
    asm("tanh.approx.f32 %0, %1;" : "=f"(r) : "f"(v));
    return r;
}
#define LDSM4(r0, r1, r2, r3, a)                                            \
    asm volatile("ldmatrix.sync.aligned.m8n8.x4.shared.b16 {%0,%1,%2,%3}, [%4];" \
        : "=r"(r0), "=r"(r1), "=r"(r2), "=r"(r3) : "r"(a))
#define MMA16816(d0, d1, d2, d3, a0, a1, a2, a3, b0, b1)                    \
    asm volatile("mma.sync.aligned.m16n8k16.row.col.f32.f16.f16.f32 "       \
        "{%0,%1,%2,%3}, {%4,%5,%6,%7}, {%8,%9}, {%0,%1,%2,%3};"             \
        : "+f"(d0), "+f"(d1), "+f"(d2), "+f"(d3)                            \
        : "r"(a0), "r"(a1), "r"(a2), "r"(a3), "r"(b0), "r"(b1))
#define CP_ASYNC16(dst, src)                                                \
    asm volatile("cp.async.cg.shared.global [%0], [%1], 16;"                \
        :: "r"(dst), "l"(src) : "memory")
#define CP_COMMIT() asm volatile("cp.async.commit_group;" ::: "memory")
#define CP_WAIT0()  asm volatile("cp.async.wait_group 0;" ::: "memory")

// ---------------------------------------------------------------- setup
__global__ void table_kernel(const float* __restrict__ emb,
                             const float* __restrict__ W_ih,
                             const float* __restrict__ b_ih,
                             const float* __restrict__ b_hh) {
    __shared__ float embs[32 * 65];
    __shared__ float wch[64 * 129];
    const int g  = threadIdx.x;
    const int gt = blockIdx.x, vt = blockIdx.y;
    float acc[32];
#pragma unroll
    for (int v = 0; v < 32; v++) acc[v] = 0.f;

    for (int ch = 0; ch < 4; ch++) {
        __syncthreads();
        for (int i = g; i < 2048; i += 128) {
            int v = i >> 6, e = i & 63;
            embs[v * 65 + e] = emb[(vt * 32 + v) * 256 + ch * 64 + e];
        }
        {
            const float4* src = (const float4*)(W_ih + (size_t)(gt * 128 + g) * 256 + ch * 64);
#pragma unroll
            for (int q = 0; q < 16; q++) {
                float4 w = src[q];
                wch[(q * 4 + 0) * 129 + g] = w.x;
                wch[(q * 4 + 1) * 129 + g] = w.y;
                wch[(q * 4 + 2) * 129 + g] = w.z;
                wch[(q * 4 + 3) * 129 + g] = w.w;
            }
        }
        __syncthreads();
#pragma unroll 4
        for (int e = 0; e < 64; e++) {
            float w = wch[e * 129 + g];
#pragma unroll
            for (int v = 0; v < 32; v++) acc[v] += w * embs[v * 65 + e];
        }
    }
    int col = gt * 128 + g;
    float bias = b_ih[col] + b_hh[col];
#pragma unroll
    for (int v = 0; v < 32; v++) {
        int tok = vt * 32 + v;
        g_table[(size_t)tok * GG + col] = (tok == 0 ? 0.f : acc[v]) + bias;
    }
}

__global__ void pack_w_kernel(const float* __restrict__ Whh) {
    int idx = blockIdx.x * 256 + threadIdx.x;
    g_W[idx] = __float2half(Whh[idx]);
}

__global__ void init_kernel(const float* __restrict__ h0) {
    int i = blockIdx.x * 256 + threadIdx.x;
    g_h[1][i] = __float2half(h0[i]);          // t=0 reads buffer (0+1)&1 = 1
    if (i < 4) g_cnt[i] = 0;
}

// ---------------------------------------------------------------- main
__global__ void __launch_bounds__(NTHR, 1)
step_all(const int* __restrict__ x,
         const float* __restrict__ c0,
         float* __restrict__ out) {
    extern __shared__ __align__(16) unsigned char sm[];
    const uint32_t smb = smem_u32(sm);
    float* gs = (float*)(sm + OFF_GS);        // [32 rows][pitch 66]

    const int tid   = threadIdx.x;
    const int bid   = blockIdx.x;
    const int lane  = tid & 31;
    const int warp  = tid >> 5;
    const int warpM = warp & 1;               // 2 x m16
    const int warpN = (warp >> 1) & 3;        // 4 x n16
    const int warpK = warp >> 3;              // 2-way split-K
    const int khalf2 = warpK * 256;           // byte offset of 128-k half

    // ---- stage W slice once (block rows: gate*8 + jj) ----
#pragma unroll
    for (int j = 0; j < 8; j++) {
        int i = j * NTHR + tid;               // 4096 float4
        int row = i >> 7, q = i & 127;
        int grow = (row >> 3) * HH + bid * 8 + (row & 7);
        *(float4*)(sm + OFF_W + row * WP_B + q * 16) =
            __ldcg((const float4*)(g_W + (size_t)grow * HH) + q);
    }

    // ---- per-lane ldmatrix address bases ----
    const int rowA  = warpM * 16 + (lane & 15);
    const int kOffA = (lane >> 4) * 8;
    const uint32_t aBase = smb + OFF_W + rowA * WP_B + kOffA * 2 + khalf2;
    const int nB    = warpN * 16 + ((lane >> 4) & 1) * 8 + (lane & 7);
    const int kOffB = ((lane >> 3) & 1) * 8;
    const uint32_t bBase0 = smb + OFF_HS0 + nB * HP_B + kOffB * 2 + khalf2;
    const uint32_t bBase1 = smb + OFF_HS1 + nB * HP_B + kOffB * 2 + khalf2;

    // cell state: 1 cell per thread (unit jj, batch bb)
    const int jj = tid & 7, bb = tid >> 3;
    float creg = c0[bb * HH + bid * 8 + jj];
    const int J  = bid * 8 + jj;
    const int cn = bid >> 5;                  // this block's producer chunk

    __syncthreads();

#pragma unroll 1
    for (int t = 0; t < TT; t++) {
        const __half* __restrict__ hh = g_h[(t + 1) & 1];

        // early per-thread prefetch: token + the 4 table entries for the cell
        const int tok = __ldg(&x[bb * TT + t]);
        const float* trow = g_table + (size_t)tok * GG + J;
        float tb0 = __ldg(trow);
        float tb1 = __ldg(trow + HH);
        float tb2 = __ldg(trow + 2 * HH);
        float tb3 = __ldg(trow + 3 * HH);

        float d00=0,d01=0,d02=0,d03=0, d10=0,d11=0,d12=0,d13=0;
        const unsigned need = 32u * (unsigned)t;

        // rotated schedule: consume chunks cn, cn+1, cn+2, cn+3 (mod 4)
        if (t > 0 && tid == 0) { while (ld_acq(&g_cnt[cn]) < need) { } }
        __syncthreads();
        {   // prefetch first chunk (cn) -> hs0
            const __half* src = hh + cn * 256;
#pragma unroll
            for (int p = 0; p < 4; p++) {
                int i = p * NTHR + tid;
                int row = i >> 5, kq = i & 31;
                CP_ASYNC16(smb + OFF_HS0 + row * HP_B + kq * 16,
                           src + row * HH + kq * 8);
            }
            CP_COMMIT();
        }

#pragma unroll 1
        for (int i4 = 0; i4 < 4; i4++) {
            const int cnext = (cn + i4 + 1) & 3;
            if (i4 < 3 && t > 0 && tid == 0) {
                while (ld_acq(&g_cnt[cnext]) < need) { }
            }
            CP_WAIT0();
            __syncthreads();
            if (i4 < 3) {
                const __half* src = hh + cnext * 256;
                uint32_t dst = ((i4 + 1) & 1) ? (smb + OFF_HS1) : (smb + OFF_HS0);
#pragma unroll
                for (int p = 0; p < 4; p++) {
                    int i = p * NTHR + tid;
                    int row = i >> 5, kq = i & 31;
                    CP_ASYNC16(dst + row * HP_B + kq * 16,
                               src + row * HH + kq * 8);
                }
                CP_COMMIT();
            }
            const uint32_t bB = (i4 & 1) ? bBase1 : bBase0;
            const uint32_t aOff = (uint32_t)((cn + i4) & 3) * 512;  // k*2B
#pragma unroll
            for (int s = 0; s < 8; s++) {
                uint32_t a0,a1,a2,a3, b0,b1,b2,b3;
                LDSM4(a0,a1,a2,a3, aBase + aOff + s * 32);
                LDSM4(b0,b1,b2,b3, bB + s * 32);
                MMA16816(d00,d01,d02,d03, a0,a1,a2,a3, b0,b1);
                MMA16816(d10,d11,d12,d13, a0,a1,a2,a3, b2,b3);
            }
        }

        // ---- split-K reduce into gs[row][b] ----
        const int r0  = warpM * 16 + (lane >> 2);
        const int c0i = warpN * 16 + (lane & 3) * 2;
        if (warpK == 1) {
            *(float2*)(gs + (r0    ) * 66 + c0i    ) = make_float2(d00, d01);
            *(float2*)(gs + (r0 + 8) * 66 + c0i    ) = make_float2(d02, d03);
            *(float2*)(gs + (r0    ) * 66 + c0i + 8) = make_float2(d10, d11);
            *(float2*)(gs + (r0 + 8) * 66 + c0i + 8) = make_float2(d12, d13);
        }
        __syncthreads();
        if (warpK == 0) {
            float2* p;
            p = (float2*)(gs + (r0    ) * 66 + c0i    ); p->x += d00; p->y += d01;
            p = (float2*)(gs + (r0 + 8) * 66 + c0i    ); p->x += d02; p->y += d03;
            p = (float2*)(gs + (r0    ) * 66 + c0i + 8); p->x += d10; p->y += d11;
            p = (float2*)(gs + (r0 + 8) * 66 + c0i + 8); p->x += d12; p->y += d13;
        }
        __syncthreads();

        // ---- fused LSTM cell: 1 cell per thread (HW activations) ----
        __half* __restrict__ nh = g_h[t & 1];
        {
            float ipre = gs[(0 * 8 + jj) * 66 + bb] + tb0;
            float fpre = gs[(1 * 8 + jj) * 66 + bb] + tb1;
            float gpre = gs[(2 * 8 + jj) * 66 + bb] + tb2;
            float opre = gs[(3 * 8 + jj) * 66 + bb] + tb3;
            float isg = fast_sigmoid(ipre);
            float fsg = fast_sigmoid(fpre);
            float gth = fast_tanh(gpre);
            float osg = fast_sigmoid(opre);
            float cv = fsg * creg + isg * gth;
            creg = cv;
            float hv = osg * fast_tanh(cv);
            nh[bb * HH + J] = __float2half(hv);
            if (t == TT - 1) out[bb * HH + J] = hv;
        }

        // ---- signal this block's chunk written for step t (release) ----
        __syncthreads();
        if (t < TT - 1 && tid == 0) {
            red_release(&g_cnt[cn], 1u);
        }
    }
}

// ---------------------------------------------------------------------------
extern "C" void kernel_launch(void* const* d_in, const int* in_sizes, int n_in,
                              void* d_out, int out_size) {
    const int*   x   = (const int*)  d_in[0];
    const float* emb = (const float*)d_in[1];
    const float* Wih = (const float*)d_in[2];
    const float* Whh = (const float*)d_in[3];
    const float* bih = (const float*)d_in[4];
    const float* bhh = (const float*)d_in[5];
    const float* h0  = (const float*)d_in[6];
    const float* c0  = (const float*)d_in[7];
    float*       out = (float*)d_out;

    static int attr_set = 0;
    if (!attr_set) {
        cudaFuncSetAttribute(step_all,
                             cudaFuncAttributeMaxDynamicSharedMemorySize,
                             SMEM_BYTES);
        attr_set = 1;
    }

    table_kernel<<<dim3(32, 8), 128>>>(emb, Wih, bih, bhh);
    pack_w_kernel<<<(GG * HH) / 256, 256>>>(Whh);
    init_kernel<<<(BB * HH) / 256, 256>>>(h0);
    step_all<<<NBLK, NTHR, SMEM_BYTES>>>(x, c0, out);
}